// round 10
// baseline (speedup 1.0000x reference)
#include <cuda_runtime.h>
#include <cstdint>
#include <math.h>

// ---------------------------------------------------------------------------
// B=32, P=1024, HID=512, H=8, D=64, MEM=64, RANK=64
// coeffs[b,p,q] = sum_{i<16} F[b,p,i]*Hh[b,q,i] + Hh[b,q,16],  Hh = G.[F,1]
// 2 launches: kStatsFeat (stats via 24-node Chebyshev + features -> F, G),
//             kGemm (Hh on the fly + bilinear GEMM).
// ---------------------------------------------------------------------------

#define Bx 32
#define Pn 1024
#define Hn 8
#define NCH 24

__device__ float g_G[17 * 17];
__device__ float g_F[(size_t)Bx * 16 * Pn];   // [b][i][p]

// ---------------------------------------------------------------------------
// Kernel 1: fused stats + features.
// grid (9, 32), 512 threads.
//   bx < 8 : per-batch Chebyshev stats (block-local) + features for 128 p.
//   bx == 8, by == 0 : 17x17 bilinear form G.
// ---------------------------------------------------------------------------
__global__ void __launch_bounds__(512) kStatsFeat(
    const float* __restrict__ x,
    const float* __restrict__ w_k, const float* __restrict__ w_mem,
    const float* __restrict__ w_u, const float* __restrict__ b_u,
    const float* __restrict__ w_v2, const float* __restrict__ b_v2,
    const float* __restrict__ w_v, const float* __restrict__ b_v,
    const float* __restrict__ w_q, const float* __restrict__ b_q)
{
    const int tid = threadIdx.x;
    const int lane = tid & 31, wid = tid >> 5;
    const float PI = 3.14159265358979323846f;

    if (blockIdx.x == 8) {
        if (blockIdx.y != 0) return;
        // ---- G matrix ----
        __shared__ float sWU[64][17];
        __shared__ float sWV[64][17];
        for (int idx = tid; idx < 64 * 16; idx += 512) {
            int r = idx >> 4, i = idx & 15, hh = i & 7;
            const float* col = (i < 8) ? w_v : b_v;
            float su = 0.f, sv = 0.f;
            #pragma unroll 8
            for (int d = 0; d < 64; d++) {
                float c = col[hh * 64 + d];
                su = fmaf(w_u[r * 512 + hh * 64 + d], c, su);
                sv = fmaf(w_v2[r * 512 + hh * 64 + d], c, sv);
            }
            sWU[r][i] = su;
            sWV[r][i] = sv;
        }
        if (tid < 64) { sWU[tid][16] = b_u[tid]; sWV[tid][16] = b_v2[tid]; }
        __syncthreads();
        for (int idx = tid; idx < 289; idx += 512) {
            int i = idx / 17, j = idx % 17;
            float s = 0.f;
            #pragma unroll 8
            for (int r = 0; r < 64; r++)
                s = fmaf(sWU[r][i], sWV[r][j], s);
            g_G[idx] = s;
        }
        return;
    }

    // ---- per-batch stats + features ----
    const int b = blockIdx.y;
    const int p0 = blockIdx.x * 128;

    __shared__ __align__(16) float sx[Pn];
    __shared__ __align__(16) float swq[512];
    __shared__ __align__(16) float sbq[512];
    __shared__ __align__(16) float swv[512];
    __shared__ __align__(16) float sbv[512];
    __shared__ float sFn[NCH], sGn[NCH];
    __shared__ float scf[NCH], scg[NCH];
    __shared__ float sNodes[NCH];
    __shared__ float sred[16];
    __shared__ float sAmax;
    __shared__ float sTm[512], sT2[512];
    __shared__ float sS1[8], sS2[8];

    sx[tid] = x[b * Pn + tid];
    sx[tid + 512] = x[b * Pn + tid + 512];
    swq[tid] = w_q[tid]; sbq[tid] = b_q[tid];
    swv[tid] = w_v[tid]; sbv[tid] = b_v[tid];

    // a[h,m], thread = (h,m)
    const int h8 = tid >> 6, m = tid & 63;
    float a = 0.f;
    #pragma unroll 8
    for (int d = 0; d < 64; d++)
        a = fmaf(w_k[h8 * 64 + d], w_mem[m * 64 + d], a);

    // amax = max |a|
    float am = fabsf(a);
    #pragma unroll
    for (int off = 16; off; off >>= 1)
        am = fmaxf(am, __shfl_down_sync(0xffffffffu, am, off));
    if (lane == 0) sred[wid] = am;
    __syncthreads();
    if (tid == 0) {
        float M = sred[0];
        #pragma unroll
        for (int i = 1; i < 16; i++) M = fmaxf(M, sred[i]);
        sAmax = M;
    }
    __syncthreads();
    const float amax = sAmax;
    if (tid < NCH)
        sNodes[tid] = amax * cosf((2 * tid + 1) * (PI / (2 * NCH)));
    __syncthreads();

    // node sums (MUFU __expf)
    for (int j = wid; j < NCH; j += 16) {
        const float aj = sNodes[j];
        float num = 0.f, den = 0.f;
        #pragma unroll 8
        for (int p = lane; p < Pn; p += 32) {
            float xv = sx[p];
            float e = __expf(aj * xv);
            den += e;
            num = fmaf(xv, e, num);
        }
        #pragma unroll
        for (int off = 16; off; off >>= 1) {
            num += __shfl_down_sync(0xffffffffu, num, off);
            den += __shfl_down_sync(0xffffffffu, den, off);
        }
        if (lane == 0) { sFn[j] = den; sGn[j] = num; }
    }
    __syncthreads();

    // Chebyshev coefficient transform (threads 0..47)
    if (tid < 2 * NCH) {
        const int k = (tid < NCH) ? tid : (tid - NCH);
        const float* src = (tid < NCH) ? sFn : sGn;
        float s = 0.f;
        #pragma unroll
        for (int j = 0; j < NCH; j++)
            s = fmaf((2.0f / NCH) * cosf(k * (2 * j + 1) * (PI / (2 * NCH))), src[j], s);
        if (tid < NCH) scf[k] = s; else scg[k] = s;
    }
    __syncthreads();

    // Clenshaw -> T[h,m], then S1/S2
    {
        const float t = a / amax;
        const float t2 = 2.f * t;
        float c1 = 0.f, c2 = 0.f, d1 = 0.f, d2 = 0.f;
        #pragma unroll
        for (int k = NCH - 1; k >= 1; k--) {
            float nb = fmaf(t2, c1, -c2) + scf[k];
            c2 = c1; c1 = nb;
            float nd = fmaf(t2, d1, -d2) + scg[k];
            d2 = d1; d1 = nd;
        }
        const float f = fmaf(t, c1, -c2) + 0.5f * scf[0];
        const float g = fmaf(t, d1, -d2) + 0.5f * scg[0];
        const float T = g / f;
        sTm[tid] = T;
        sT2[tid] = T * T;
    }
    __syncthreads();
    if (wid < 8) {
        float s1 = sTm[wid * 64 + lane] + sTm[wid * 64 + 32 + lane];
        float s2 = sT2[wid * 64 + lane] + sT2[wid * 64 + 32 + lane];
        #pragma unroll
        for (int off = 16; off; off >>= 1) {
            s1 += __shfl_down_sync(0xffffffffu, s1, off);
            s2 += __shfl_down_sync(0xffffffffu, s2, off);
        }
        if (lane == 0) { sS1[wid] = s1; sS2[wid] = s2; }
    }
    __syncthreads();

    // ---- features for p in [p0, p0+128), thread=(h, pl), 2 p per thread ----
    const int h = tid >> 6, pl = tid & 63;
    const float4* wq4 = (const float4*)&swq[h * 64];
    const float4* bq4 = (const float4*)&sbq[h * 64];
    const float4* wv4 = (const float4*)&swv[h * 64];
    const float4* bv4 = (const float4*)&sbv[h * 64];
    const float s1 = sS1[h], s2 = sS2[h];
    const size_t baseF = ((size_t)b * 16) * Pn;

    #pragma unroll
    for (int rep = 0; rep < 2; rep++) {
        const int p = p0 + rep * 64 + pl;
        const float xx = sx[p];
        float a1 = 0.f, a2 = 0.f;
        #pragma unroll
        for (int d4 = 0; d4 < 16; d4++) {
            float4 q = wq4[d4], bq = bq4[d4], wv = wv4[d4], bv = bv4[d4];
            float v, qf;
            v = fmaf(xx, q.x, bq.x); qf = (v > 0.f) ? (v + 1.f) : __expf(v);
            a1 = fmaf(qf, wv.x, a1); a2 = fmaf(qf, bv.x, a2);
            v = fmaf(xx, q.y, bq.y); qf = (v > 0.f) ? (v + 1.f) : __expf(v);
            a1 = fmaf(qf, wv.y, a1); a2 = fmaf(qf, bv.y, a2);
            v = fmaf(xx, q.z, bq.z); qf = (v > 0.f) ? (v + 1.f) : __expf(v);
            a1 = fmaf(qf, wv.z, a1); a2 = fmaf(qf, bv.z, a2);
            v = fmaf(xx, q.w, bq.w); qf = (v > 0.f) ? (v + 1.f) : __expf(v);
            a1 = fmaf(qf, wv.w, a1); a2 = fmaf(qf, bv.w, a2);
        }
        g_F[baseF + (size_t)h * Pn + p]       = fmaf(a1, s2, a2 * s1);   // alpha
        g_F[baseF + (size_t)(8 + h) * Pn + p] = fmaf(a1, s1, 64.f * a2); // beta
    }
}

// ---------------------------------------------------------------------------
// Kernel 2: bilinear GEMM with on-the-fly Hh = G.[F,1] for the q-tile.
// ---------------------------------------------------------------------------
#define FMA2(acc64, a64, b64) \
    asm("fma.rn.f32x2 %0, %1, %2, %0;" : "+l"(acc64) : "l"(a64), "l"(b64))
#define UNPACK2(lo, hi, in64) do { \
    unsigned _u0, _u1; \
    asm("mov.b64 {%0, %1}, %2;" : "=r"(_u0), "=r"(_u1) : "l"(in64)); \
    lo = __uint_as_float(_u0); hi = __uint_as_float(_u1); } while (0)

__global__ void __launch_bounds__(256) kGemm(float* __restrict__ out)
{
    const int b = blockIdx.z;
    const int tq0 = blockIdx.x * 64;
    const int tp0 = blockIdx.y * 128;

    __shared__ __align__(16) float sFd[16][256];  // p-tile F, duplicated pairs
    __shared__ __align__(16) float sFq[16][64];   // q-tile F
    __shared__ __align__(16) float sHh[17][64];   // Hh tile (computed here)
    __shared__ float sG[289];

    const int tid = threadIdx.x;
    const int lane = tid & 31, w = tid >> 5;
    const float* Fb = g_F + ((size_t)b * 16) * Pn;

    // p-tile (duplicated)
    #pragma unroll
    for (int rep = 0; rep < 2; rep++) {
        int idx = tid + rep * 256;
        int row = idx >> 5, c4 = (idx & 31) << 2;
        float4 v = *(const float4*)&Fb[(size_t)row * Pn + tp0 + c4];
        *(float4*)&sFd[row][c4 * 2]     = make_float4(v.x, v.x, v.y, v.y);
        *(float4*)&sFd[row][c4 * 2 + 4] = make_float4(v.z, v.z, v.w, v.w);
    }
    // q-tile
    {
        int row = tid >> 4, c4 = (tid & 15) << 2;
        *(float4*)&sFq[row][c4] = *(const float4*)&Fb[(size_t)row * Pn + tq0 + c4];
    }
    for (int i = tid; i < 289; i += 256) sG[i] = g_G[i];
    __syncthreads();

    // Hh[i][q] = G[i][16] + sum_j G[i][j] * Fq[j][q]
    for (int o = tid; o < 17 * 64; o += 256) {
        int i = o >> 6, q = o & 63;
        float s = sG[i * 17 + 16];
        #pragma unroll
        for (int j = 0; j < 16; j++)
            s = fmaf(sG[i * 17 + j], sFq[j][q], s);
        sHh[i][q] = s;
    }
    __syncthreads();

    unsigned long long bq[16];
    #pragma unroll
    for (int k = 0; k < 16; k++)
        bq[k] = *(const unsigned long long*)&sHh[k][2 * lane];
    const unsigned long long hbias = *(const unsigned long long*)&sHh[16][2 * lane];

    unsigned long long acc[16];
    #pragma unroll
    for (int r = 0; r < 16; r++) acc[r] = hbias;

    const int rowbase = w * 16;
    #pragma unroll
    for (int k = 0; k < 16; k++) {
        const float* fr = &sFd[k][rowbase * 2];
        #pragma unroll
        for (int rp = 0; rp < 8; rp++) {
            ulonglong2 ad = *(const ulonglong2*)&fr[rp * 4];
            FMA2(acc[2 * rp],     ad.x, bq[k]);
            FMA2(acc[2 * rp + 1], ad.y, bq[k]);
        }
    }

    float* outb = out + (size_t)b * Pn * Pn + (size_t)(tp0 + rowbase) * Pn + tq0 + 2 * lane;
    #pragma unroll
    for (int r = 0; r < 16; r++) {
        float2 v;
        UNPACK2(v.x, v.y, acc[r]);
        *(float2*)&outb[(size_t)r * Pn] = v;
    }
}

// ---------------------------------------------------------------------------
// inputs: 0 x, 1 w_q, 2 b_q, 3 w_k, 4 b_k(unused), 5 w_v, 6 b_v, 7 w_mem,
//         8 w_u, 9 b_u, 10 w_v2, 11 b_v2
// ---------------------------------------------------------------------------
extern "C" void kernel_launch(void* const* d_in, const int* in_sizes, int n_in,
                              void* d_out, int out_size)
{
    const float* x    = (const float*)d_in[0];
    const float* w_q  = (const float*)d_in[1];
    const float* b_q  = (const float*)d_in[2];
    const float* w_k  = (const float*)d_in[3];
    const float* w_v  = (const float*)d_in[5];
    const float* b_v  = (const float*)d_in[6];
    const float* w_mem = (const float*)d_in[7];
    const float* w_u  = (const float*)d_in[8];
    const float* b_u  = (const float*)d_in[9];
    const float* w_v2 = (const float*)d_in[10];
    const float* b_v2 = (const float*)d_in[11];
    float* out = (float*)d_out;

    kStatsFeat<<<dim3(9, Bx), 512>>>(x, w_k, w_mem, w_u, b_u, w_v2, b_v2,
                                     w_v, b_v, w_q, b_q);
    kGemm<<<dim3(Pn / 64, Pn / 128, Bx), 256>>>(out);
}

// round 11
// speedup vs baseline: 1.3186x; 1.3186x over previous
#include <cuda_runtime.h>
#include <cstdint>
#include <math.h>

// ---------------------------------------------------------------------------
// B=32, P=1024, HID=512, H=8, D=64, MEM=64, RANK=64
// coeffs[b,p,q] = sum_{i<16} F[b,p,i]*Hh[b,q,i] + Hh[b,q,16],  Hh = G.[F,1]
// 3 launches: kPre (Chebyshev stats + G), kFeat (features -> g_F, g_Hh),
//             kGemm (register-B bilinear GEMM, q-quad per lane).
// ---------------------------------------------------------------------------

#define Bx 32
#define Pn 1024
#define Hn 8
#define NCH 24

__device__ float g_G[17 * 17];
__device__ float g_S1[Bx * Hn];
__device__ float g_S2[Bx * Hn];
__device__ float g_F[(size_t)Bx * 16 * Pn];   // [b][i][p]
__device__ float g_Hh[(size_t)Bx * 17 * Pn];  // [b][i][p]

// ---------------------------------------------------------------------------
// Kernel 1: prelude. blocks 0..31: per-batch Chebyshev stats -> S1,S2.
// block 32: 17x17 bilinear form G.
// ---------------------------------------------------------------------------
__global__ void __launch_bounds__(512) kPre(
    const float* __restrict__ x,
    const float* __restrict__ w_k, const float* __restrict__ w_mem,
    const float* __restrict__ w_u, const float* __restrict__ b_u,
    const float* __restrict__ w_v2, const float* __restrict__ b_v2,
    const float* __restrict__ w_v, const float* __restrict__ b_v)
{
    const int tid = threadIdx.x;
    const int lane = tid & 31, wid = tid >> 5;
    const float PI = 3.14159265358979323846f;

    if (blockIdx.x == 32) {
        __shared__ float sWU[64][17];
        __shared__ float sWV[64][17];
        for (int idx = tid; idx < 64 * 16; idx += 512) {
            int r = idx >> 4, i = idx & 15, hh = i & 7;
            const float* col = (i < 8) ? w_v : b_v;
            float su = 0.f, sv = 0.f;
            #pragma unroll 8
            for (int d = 0; d < 64; d++) {
                float c = col[hh * 64 + d];
                su = fmaf(w_u[r * 512 + hh * 64 + d], c, su);
                sv = fmaf(w_v2[r * 512 + hh * 64 + d], c, sv);
            }
            sWU[r][i] = su;
            sWV[r][i] = sv;
        }
        if (tid < 64) { sWU[tid][16] = b_u[tid]; sWV[tid][16] = b_v2[tid]; }
        __syncthreads();
        for (int idx = tid; idx < 289; idx += 512) {
            int i = idx / 17, j = idx % 17;
            float s = 0.f;
            #pragma unroll 8
            for (int r = 0; r < 64; r++)
                s = fmaf(sWU[r][i], sWV[r][j], s);
            g_G[idx] = s;
        }
        return;
    }

    const int b = blockIdx.x;
    __shared__ __align__(16) float sx[Pn];
    __shared__ float sFn[NCH], sGn[NCH];
    __shared__ float scf[NCH], scg[NCH];
    __shared__ float sNodes[NCH];
    __shared__ float sred[16];
    __shared__ float sAmax;
    __shared__ float sTm[512], sT2[512];

    sx[tid] = x[b * Pn + tid];
    sx[tid + 512] = x[b * Pn + tid + 512];

    // a[h,m], thread = (h,m)
    const int h8 = tid >> 6, m = tid & 63;
    float a = 0.f;
    #pragma unroll 8
    for (int d = 0; d < 64; d++)
        a = fmaf(w_k[h8 * 64 + d], w_mem[m * 64 + d], a);

    float am = fabsf(a);
    #pragma unroll
    for (int off = 16; off; off >>= 1)
        am = fmaxf(am, __shfl_down_sync(0xffffffffu, am, off));
    if (lane == 0) sred[wid] = am;
    __syncthreads();
    if (tid == 0) {
        float M = sred[0];
        #pragma unroll
        for (int i = 1; i < 16; i++) M = fmaxf(M, sred[i]);
        sAmax = M;
    }
    __syncthreads();
    const float amax = sAmax;
    if (tid < NCH)
        sNodes[tid] = amax * cosf((2 * tid + 1) * (PI / (2 * NCH)));
    __syncthreads();

    // node sums (MUFU __expf)
    for (int j = wid; j < NCH; j += 16) {
        const float aj = sNodes[j];
        float num = 0.f, den = 0.f;
        #pragma unroll 8
        for (int p = lane; p < Pn; p += 32) {
            float xv = sx[p];
            float e = __expf(aj * xv);
            den += e;
            num = fmaf(xv, e, num);
        }
        #pragma unroll
        for (int off = 16; off; off >>= 1) {
            num += __shfl_down_sync(0xffffffffu, num, off);
            den += __shfl_down_sync(0xffffffffu, den, off);
        }
        if (lane == 0) { sFn[j] = den; sGn[j] = num; }
    }
    __syncthreads();

    if (tid < 2 * NCH) {
        const int k = (tid < NCH) ? tid : (tid - NCH);
        const float* src = (tid < NCH) ? sFn : sGn;
        float s = 0.f;
        #pragma unroll
        for (int j = 0; j < NCH; j++)
            s = fmaf((2.0f / NCH) * cosf(k * (2 * j + 1) * (PI / (2 * NCH))), src[j], s);
        if (tid < NCH) scf[k] = s; else scg[k] = s;
    }
    __syncthreads();

    {
        const float t = a / amax;
        const float t2 = 2.f * t;
        float c1 = 0.f, c2 = 0.f, d1 = 0.f, d2 = 0.f;
        #pragma unroll
        for (int k = NCH - 1; k >= 1; k--) {
            float nb = fmaf(t2, c1, -c2) + scf[k];
            c2 = c1; c1 = nb;
            float nd = fmaf(t2, d1, -d2) + scg[k];
            d2 = d1; d1 = nd;
        }
        const float f = fmaf(t, c1, -c2) + 0.5f * scf[0];
        const float g = fmaf(t, d1, -d2) + 0.5f * scg[0];
        const float T = g / f;
        sTm[tid] = T;
        sT2[tid] = T * T;
    }
    __syncthreads();
    if (wid < 8) {
        float s1 = sTm[wid * 64 + lane] + sTm[wid * 64 + 32 + lane];
        float s2 = sT2[wid * 64 + lane] + sT2[wid * 64 + 32 + lane];
        #pragma unroll
        for (int off = 16; off; off >>= 1) {
            s1 += __shfl_down_sync(0xffffffffu, s1, off);
            s2 += __shfl_down_sync(0xffffffffu, s2, off);
        }
        if (lane == 0) { g_S1[b * Hn + wid] = s1; g_S2[b * Hn + wid] = s2; }
    }
}

// ---------------------------------------------------------------------------
// Kernel 2: features (direct elu). grid (Pn/64, Bx), 512 thr.
// Writes g_F and g_Hh.
// ---------------------------------------------------------------------------
__global__ void __launch_bounds__(512) kFeat(
    const float* __restrict__ x,
    const float* __restrict__ w_q, const float* __restrict__ b_q,
    const float* __restrict__ w_v, const float* __restrict__ b_v)
{
    __shared__ __align__(16) float swq[512];
    __shared__ __align__(16) float sbq[512];
    __shared__ __align__(16) float swv[512];
    __shared__ __align__(16) float sbv[512];
    __shared__ float sG[289];
    __shared__ float sS1[8], sS2[8];
    __shared__ float sF[17][64];
    __shared__ float sxv[64];

    const int b = blockIdx.y, tid = threadIdx.x;
    const int p0 = blockIdx.x * 64;

    swq[tid] = w_q[tid]; sbq[tid] = b_q[tid];
    swv[tid] = w_v[tid]; sbv[tid] = b_v[tid];
    if (tid < 289) sG[tid] = g_G[tid];
    if (tid < 8) { sS1[tid] = g_S1[b * Hn + tid]; sS2[tid] = g_S2[b * Hn + tid]; }
    if (tid < 64) sxv[tid] = x[b * Pn + p0 + tid];
    __syncthreads();

    const int h = tid >> 6, pl = tid & 63;
    const float xv = sxv[pl];
    const float4* wq4 = (const float4*)&swq[h * 64];
    const float4* bq4 = (const float4*)&sbq[h * 64];
    const float4* wv4 = (const float4*)&swv[h * 64];
    const float4* bv4 = (const float4*)&sbv[h * 64];

    float a1 = 0.f, a2 = 0.f;
    #pragma unroll
    for (int d4 = 0; d4 < 16; d4++) {
        float4 q = wq4[d4], bq = bq4[d4], wv = wv4[d4], bv = bv4[d4];
        float v, qf;
        v = fmaf(xv, q.x, bq.x); qf = (v > 0.f) ? (v + 1.f) : __expf(v);
        a1 = fmaf(qf, wv.x, a1); a2 = fmaf(qf, bv.x, a2);
        v = fmaf(xv, q.y, bq.y); qf = (v > 0.f) ? (v + 1.f) : __expf(v);
        a1 = fmaf(qf, wv.y, a1); a2 = fmaf(qf, bv.y, a2);
        v = fmaf(xv, q.z, bq.z); qf = (v > 0.f) ? (v + 1.f) : __expf(v);
        a1 = fmaf(qf, wv.z, a1); a2 = fmaf(qf, bv.z, a2);
        v = fmaf(xv, q.w, bq.w); qf = (v > 0.f) ? (v + 1.f) : __expf(v);
        a1 = fmaf(qf, wv.w, a1); a2 = fmaf(qf, bv.w, a2);
    }
    const float s1 = sS1[h], s2 = sS2[h];
    sF[h][pl]     = fmaf(a1, s2, a2 * s1);   // alpha
    sF[8 + h][pl] = fmaf(a1, s1, 64.f * a2); // beta
    if (h == 0) sF[16][pl] = 1.f;
    __syncthreads();

    {
        size_t baseF = ((size_t)b * 16) * Pn + p0;
        int i = tid >> 6, pl2 = tid & 63;
        g_F[baseF + (size_t)i * Pn + pl2] = sF[i][pl2];
        g_F[baseF + (size_t)(i + 8) * Pn + pl2] = sF[i + 8][pl2];
    }
    {
        size_t baseH = ((size_t)b * 17) * Pn + p0;
        for (int o = tid; o < 17 * 64; o += 512) {
            int i = o >> 6, pl2 = o & 63;
            float s = 0.f;
            #pragma unroll
            for (int j = 0; j < 17; j++)
                s = fmaf(sG[i * 17 + j], sF[j][pl2], s);
            g_Hh[baseH + (size_t)i * Pn + pl2] = s;
        }
    }
}

// ---------------------------------------------------------------------------
// Kernel 3: bilinear GEMM v3.
// Block: 256 thr (8 warps), tile 64p x 128q. Warp: 8p x 128q.
// Lane owns a q-QUAD (4 consecutive q): each A broadcast feeds 2 FFMA2 per row
// (1:4 LDS:FFMA2 ratio). B (Hh) loaded straight from global to registers in
// two k-phases of 8 (L1/L2-resident). Epilogue: 8x STG.128.
// ---------------------------------------------------------------------------
#define FMA2(acc64, a64, b64) \
    asm("fma.rn.f32x2 %0, %1, %2, %0;" : "+l"(acc64) : "l"(a64), "l"(b64))
#define UNPACK2(lo, hi, in64) do { \
    unsigned _u0, _u1; \
    asm("mov.b64 {%0, %1}, %2;" : "=r"(_u0), "=r"(_u1) : "l"(in64)); \
    lo = __uint_as_float(_u0); hi = __uint_as_float(_u1); } while (0)

__global__ void __launch_bounds__(256) kGemm(float* __restrict__ out)
{
    const int b = blockIdx.z;
    const int tq0 = blockIdx.x * 128;
    const int tp0 = blockIdx.y * 64;

    __shared__ __align__(16) float sFd[16][128];  // 64 p, dup pairs

    const int tid = threadIdx.x;
    const int lane = tid & 31, w = tid >> 5;
    const float* Fb = g_F + ((size_t)b * 16) * Pn;
    const float* Hb = g_Hh + ((size_t)b * 17) * Pn;
    const float* HbQ = Hb + tq0 + 4 * lane;

    // fill p-tile duplicated: 16 rows x 16 float4 = 256 loads, 1 per thread
    {
        int row = tid >> 4, c4 = (tid & 15) << 2;
        float4 v = *(const float4*)&Fb[(size_t)row * Pn + tp0 + c4];
        *(float4*)&sFd[row][c4 * 2]     = make_float4(v.x, v.x, v.y, v.y);
        *(float4*)&sFd[row][c4 * 2 + 4] = make_float4(v.z, v.z, v.w, v.w);
    }

    // bias + phase-0 B (k=0..7) straight to regs
    ulonglong2 hb = *(const ulonglong2*)&HbQ[(size_t)16 * Pn];
    unsigned long long bq[8][2];
    #pragma unroll
    for (int k = 0; k < 8; k++) {
        ulonglong2 v = *(const ulonglong2*)&HbQ[(size_t)k * Pn];
        bq[k][0] = v.x; bq[k][1] = v.y;
    }
    __syncthreads();

    unsigned long long acc[8][2];
    #pragma unroll
    for (int r = 0; r < 8; r++) { acc[r][0] = hb.x; acc[r][1] = hb.y; }

    const int rb2 = w * 16;   // this warp's 8 rows, dup floats base

    #pragma unroll
    for (int k = 0; k < 8; k++) {
        const float* fr = &sFd[k][rb2];
        #pragma unroll
        for (int rp = 0; rp < 4; rp++) {
            ulonglong2 ad = *(const ulonglong2*)&fr[rp * 4];  // rows 2rp,2rp+1
            FMA2(acc[2 * rp][0],     ad.x, bq[k][0]);
            FMA2(acc[2 * rp][1],     ad.x, bq[k][1]);
            FMA2(acc[2 * rp + 1][0], ad.y, bq[k][0]);
            FMA2(acc[2 * rp + 1][1], ad.y, bq[k][1]);
        }
    }

    // phase-1 B (k=8..15)
    #pragma unroll
    for (int k = 0; k < 8; k++) {
        ulonglong2 v = *(const ulonglong2*)&HbQ[(size_t)(k + 8) * Pn];
        bq[k][0] = v.x; bq[k][1] = v.y;
    }
    #pragma unroll
    for (int k = 0; k < 8; k++) {
        const float* fr = &sFd[k + 8][rb2];
        #pragma unroll
        for (int rp = 0; rp < 4; rp++) {
            ulonglong2 ad = *(const ulonglong2*)&fr[rp * 4];
            FMA2(acc[2 * rp][0],     ad.x, bq[k][0]);
            FMA2(acc[2 * rp][1],     ad.x, bq[k][1]);
            FMA2(acc[2 * rp + 1][0], ad.y, bq[k][0]);
            FMA2(acc[2 * rp + 1][1], ad.y, bq[k][1]);
        }
    }

    float* outb = out + (size_t)b * Pn * Pn + (size_t)(tp0 + w * 8) * Pn + tq0 + 4 * lane;
    #pragma unroll
    for (int r = 0; r < 8; r++) {
        float4 v;
        UNPACK2(v.x, v.y, acc[r][0]);
        UNPACK2(v.z, v.w, acc[r][1]);
        *(float4*)&outb[(size_t)r * Pn] = v;
    }
}

// ---------------------------------------------------------------------------
// inputs: 0 x, 1 w_q, 2 b_q, 3 w_k, 4 b_k(unused), 5 w_v, 6 b_v, 7 w_mem,
//         8 w_u, 9 b_u, 10 w_v2, 11 b_v2
// ---------------------------------------------------------------------------
extern "C" void kernel_launch(void* const* d_in, const int* in_sizes, int n_in,
                              void* d_out, int out_size)
{
    const float* x    = (const float*)d_in[0];
    const float* w_q  = (const float*)d_in[1];
    const float* b_q  = (const float*)d_in[2];
    const float* w_k  = (const float*)d_in[3];
    const float* w_v  = (const float*)d_in[5];
    const float* b_v  = (const float*)d_in[6];
    const float* w_mem = (const float*)d_in[7];
    const float* w_u  = (const float*)d_in[8];
    const float* b_u  = (const float*)d_in[9];
    const float* w_v2 = (const float*)d_in[10];
    const float* b_v2 = (const float*)d_in[11];
    float* out = (float*)d_out;

    kPre<<<33, 512>>>(x, w_k, w_mem, w_u, b_u, w_v2, b_v2, w_v, b_v);
    kFeat<<<dim3(Pn / 64, Bx), 512>>>(x, w_q, b_q, w_v, b_v);
    kGemm<<<dim3(Pn / 128, Pn / 64, Bx), 256>>>(out);
}